// round 5
// baseline (speedup 1.0000x reference)
#include <cuda_runtime.h>
#include <math.h>

#define BB   128            // batch
#define TT   512            // time steps
#define HH   256            // hidden
#define XX   64             // feature / output
#define G3   768            // 3*H
#define HB   (HH * BB)      // 32768 floats per [h][b] map

// ---------------- device scratch (static: no runtime allocation) ----------------
__device__ float g_buf[(size_t)TT * HB];        // h_t history, [t][h][b]      (64 MB)
__device__ float g_hb [(size_t)(TT + 1) * HB];  // hb_{t-1} at slot t, slot0=0 (64 MB)
__device__ float g_hid[2 * HB];                 // double-buffered hidden_i [par][h][b]
__device__ float g_Wc [G3 * HH];                // W_ih @ W_out   [768][256]
__device__ float g_WoT[HH * XX];                // W_out transposed [h][x]
__device__ float g_bc [G3];                     // b_ih + W_ih @ b_out
__device__ float g_m0f[TT], g_m1f[TT];
__device__ int   g_gidx[TT], g_pidx[TT];        // -1 => zero placeholder
__device__ unsigned g_bcnt[8 * 32];             // per-group barrier counters (padded)
__device__ unsigned g_bgen[8 * 32];             // per-group generation (monotonic)

// ---------------- packed f32x2 fma (Blackwell FFMA2) ----------------
#define FMA2(d, a, b) asm("fma.rn.f32x2 %0, %1, %2, %3;" \
                          : "=l"(d) : "l"(a), "l"(b), "l"(d))
__device__ __forceinline__ float lo32(unsigned long long v) {
    return __uint_as_float((unsigned)(v & 0xffffffffull));
}
__device__ __forceinline__ float hi32(unsigned long long v) {
    return __uint_as_float((unsigned)(v >> 32));
}

// ---------------- acq/rel group barrier (no membar, no L1 flush) ----------------
__device__ __forceinline__ void group_barrier(unsigned* cnt, unsigned* gen, unsigned nctas)
{
    unsigned g;
    asm volatile("ld.relaxed.gpu.u32 %0, [%1];" : "=r"(g) : "l"(gen));
    unsigned old;
    asm volatile("atom.add.release.gpu.u32 %0, [%1], 1;" : "=r"(old) : "l"(cnt));
    if (old == nctas - 1u) {
        asm volatile("st.relaxed.gpu.u32 [%0], %1;" :: "l"(cnt), "r"(0u));
        asm volatile("st.release.gpu.u32 [%0], %1;" :: "l"(gen), "r"(g + 1u));
    } else {
        unsigned cur;
        do {
            asm volatile("ld.acquire.gpu.u32 %0, [%1];" : "=r"(cur) : "l"(gen));
        } while (cur == g);
    }
}

// ---------------- K_wc: Wc = W_ih @ W_out  + W_out transpose ----------------
__global__ void k_wc(const float* __restrict__ W_ih, const float* __restrict__ W_out)
{
    int j = blockIdx.x;
    int k = threadIdx.x;
    if (j < G3) {
        float acc = 0.f;
        #pragma unroll
        for (int x = 0; x < XX; x++)
            acc += W_ih[j * XX + x] * W_out[x * HH + k];
        g_Wc[j * HH + k] = acc;
    } else {
        int idx = (j - G3) * 256 + k;           // 64 extra blocks: 16384 elems
        int h = idx >> 6, x = idx & 63;
        g_WoT[h * XX + x] = W_out[x * HH + h];
    }
}

// ---------------- K_tab: tables + composed bias ----------------
__global__ void k_init_tables(const int* __restrict__ mask0, const int* __restrict__ mask1,
                              const int* skipp,
                              const float* __restrict__ W_ih, const float* __restrict__ b_ih,
                              const float* __restrict__ b_out)
{
    int tid = threadIdx.x;
    int skip = skipp ? skipp[0] : 4;
    for (int i = tid; i < TT; i += 256) {
        g_m0f[i] = (float)mask0[i];
        g_m1f[i] = (float)mask1[i];
        int pg = (i < skip) ? 2 * i : i - skip;
        g_gidx[i] = (pg < skip) ? -1 : (pg - skip);
        int pp = (i < skip) ? 2 * i + 1 : i - skip;
        g_pidx[i] = (pp < skip) ? -1 : (pp - skip);
    }
    for (int j = tid; j < G3; j += 256) {
        float acc = b_ih[j];
        for (int x = 0; x < XX; x++) acc += W_ih[j * XX + x] * b_out[x];
        g_bc[j] = acc;
    }
}

// ---------------- K_state: init hidden_0 / hb_{-1} ----------------
__global__ void k_init_state(const float* __restrict__ h_enc, const int* __restrict__ mask0)
{
    int idx = blockIdx.x * 256 + threadIdx.x;   // 0..32767
    int h = idx >> 7, b = idx & 127;
    float m0 = (float)mask0[0];
    g_hid[h * BB + b] = m0 * h_enc[b * HH + h]; // hidden_0 = m0[0]*h_enc (skip term zero)
    g_hb[idx] = 0.f;                            // hb_{-1} = 0  => gi_0 uses b_ih
}

// ---------------- K_main: persistent recurrence, 512 threads, k-split 2 ----------------
// smem floats: sW [256k][16h][8]  = 32768   (pairs: whh_r,wc_r,whh_z,wc_z,whh_n,wc_n,pad,pad)
//              sAct [256k][16b][2] = 8192   (pairs: hidden, hb)
//              sM0[512] sM1[512]  sGI[512] sPI[512]
#define SW_F    (256 * 16 * 8)
#define SACT_F  (256 * 16 * 2)
#define SMEM_MAIN ((SW_F + SACT_F + 4 * TT) * 4)
#define NTH 512

__global__ void __launch_bounds__(NTH, 1)
k_main(const float* __restrict__ W_hh, const float* __restrict__ b_ih,
       const float* __restrict__ b_hh, const float* __restrict__ h_enc)
{
    extern __shared__ float sm[];
    float* sW   = sm;
    float* sAct = sW + SW_F;
    float* sM0  = sAct + SACT_F;
    float* sM1  = sM0 + TT;
    int*   sGI  = (int*)(sM1 + TT);
    int*   sPI  = sGI + TT;

    const int tid = threadIdx.x;
    const int b_l = tid & 15;
    const int kq  = (tid >> 4) & 1;             // k-split half
    const int h_l = tid >> 5;                   // warp id = h feature
    const int bg  = blockIdx.x >> 4;            // barrier group = batch group
    const int hg  = blockIdx.x & 15;
    const int b0  = bg * 16;
    const int h0  = hg * 16;
    const int h   = h0 + h_l;
    const int b   = b0 + b_l;
    const int off = h * BB + b;
    const int k_base = kq * 128;

    // ---- stage weight slice once (persists across all 512 steps) ----
    for (int idx = tid; idx < 256 * 16; idx += NTH) {
        int k = idx >> 4, hl = idx & 15;
        float* d = sW + (size_t)(k * 16 + hl) * 8;
        #pragma unroll
        for (int g = 0; g < 3; g++) {
            int row = g * HH + h0 + hl;
            d[2 * g]     = W_hh[row * HH + k];
            d[2 * g + 1] = g_Wc[row * HH + k];
        }
    }
    for (int idx = tid; idx < TT; idx += NTH) {
        sM0[idx] = g_m0f[idx]; sM1[idx] = g_m1f[idx];
        sGI[idx] = g_gidx[idx]; sPI[idx] = g_pidx[idx];
    }

    // combined per-thread bias constants
    const float bhh_n = b_hh[2 * HH + h];
    const float cr0 = b_hh[h]          + b_ih[h];         // step 0 (gi bias = b_ih)
    const float cz0 = b_hh[HH + h]     + b_ih[HH + h];
    const float cn0 = b_ih[2 * HH + h];
    const float crN = b_hh[h]          + g_bc[h];         // steps >0 (gi bias = bc)
    const float czN = b_hh[HH + h]     + g_bc[HH + h];
    const float cnN = g_bc[2 * HH + h];

    float h_prev = h_enc[b * HH + h];
    __syncthreads();

    unsigned* genp = &g_bgen[bg * 32];
    unsigned* cntp = &g_bcnt[bg * 32];

    for (int i = 0; i < TT; i++) {
        // ---- tile load: hidden_i / hb_{i-1} for this CTA's 16 b's, all 256 k ----
        const float* srcH = g_hid + (i & 1) * HB;
        const float* srcB = g_hb + (size_t)i * HB;
        #pragma unroll
        for (int r = 0; r < 2; r++) {
            int idx = r * NTH + tid;            // (k, b-quad), 1024 total
            int k = idx >> 2, q = idx & 3;
            float4 hv = __ldcg((const float4*)(srcH + k * BB + b0 + q * 4));
            float4 bv = __ldcg((const float4*)(srcB + k * BB + b0 + q * 4));
            float2* d = (float2*)(sAct + (size_t)k * 32 + q * 8);
            d[0] = make_float2(hv.x, bv.x);
            d[1] = make_float2(hv.y, bv.y);
            d[2] = make_float2(hv.z, bv.z);
            d[3] = make_float2(hv.w, bv.w);
        }
        __syncthreads();

        // ---- fused dual GEMM over this thread's k half: acc.lo = gh_g, acc.hi = gi_g ----
        unsigned long long acc0 = 0ull, acc1 = 0ull, acc2 = 0ull;
        const float* ap = sAct + b_l * 2 + (size_t)k_base * 32;
        const float* wp = sW + h_l * 8 + (size_t)k_base * 128;
        #pragma unroll 8
        for (int k = 0; k < 128; k++) {
            unsigned long long a2 = *(const unsigned long long*)(ap + (size_t)k * 32);
            const float* w = wp + (size_t)k * 128;
            ulonglong2 w01 = *(const ulonglong2*)w;
            unsigned long long w2 = *(const unsigned long long*)(w + 4);
            FMA2(acc0, a2, w01.x);
            FMA2(acc1, a2, w01.y);
            FMA2(acc2, a2, w2);
        }

        // ---- merge k halves: partner lane differs in bit 4 (kq), same cell ----
        unsigned long long o0 = __shfl_xor_sync(0xffffffffu, acc0, 16);
        unsigned long long o1 = __shfl_xor_sync(0xffffffffu, acc1, 16);
        unsigned long long o2 = __shfl_xor_sync(0xffffffffu, acc2, 16);

        if (kq == 0) {
            // ---- GRU epilogue (fast-math) ----
            const float cbr = i ? crN : cr0;
            const float cbz = i ? czN : cz0;
            const float cbn = i ? cnN : cn0;
            float pre_r = lo32(acc0) + hi32(acc0) + lo32(o0) + hi32(o0) + cbr;
            float pre_z = lo32(acc1) + hi32(acc1) + lo32(o1) + hi32(o1) + cbz;
            float ghn   = lo32(acc2) + lo32(o2) + bhh_n;
            float rg = __fdividef(1.f, 1.f + __expf(-pre_r));
            float zg = __fdividef(1.f, 1.f + __expf(-pre_z));
            float pre_n = hi32(acc2) + hi32(o2) + cbn + rg * ghn;
            pre_n = fminf(fmaxf(pre_n, -15.f), 15.f);
            float e2 = __expf(2.f * pre_n);
            float ng = __fdividef(e2 - 1.f, e2 + 1.f);
            float hiddenv = sAct[((size_t)h * 16 + b_l) * 2];   // hidden_i[b][h]
            float h_new = (1.f - zg) * ng + zg * hiddenv;

            // ---- same-thread skip bookkeeping + next-step activations ----
            g_buf[(size_t)i * HB + off] = h_new;
            int pi_ = sPI[i];
            float sp = (pi_ < 0) ? 0.f : g_buf[(size_t)pi_ * HB + off];
            g_hb[(size_t)(i + 1) * HB + off] = h_prev + sp;     // hb_i
            int ip = i + 1;
            if (ip < TT) {
                int gi_ = sGI[ip];
                float sg = (gi_ < 0) ? 0.f : g_buf[(size_t)gi_ * HB + off];
                g_hid[(ip & 1) * HB + off] = sM0[ip] * h_new + sM1[ip] * sg;
            }
            h_prev = h_new;
        }

        // ---- group barrier (16 CTAs sharing this batch group) ----
        __syncthreads();
        if (tid == 0) group_barrier(cntp, genp, 16u);
        __syncthreads();
    }
}

// ---------------- K_out: out[b][t][x] = hb_t . W_out[x] + b_out ----------------
#define SMEM_OUT ((16384 + 8192) * 4)
__global__ void __launch_bounds__(256)
k_out(float* __restrict__ out, const float* __restrict__ b_out)
{
    extern __shared__ float s[];
    float* sWo = s;              // [256h][64x]
    float* sA  = s + 16384;      // [64h][128b]
    const int t = blockIdx.x;
    const int tid = threadIdx.x;
    const int bgl = tid & 31, xg = tid >> 5;   // thread: 4 b's x 8 x's

    for (int idx = tid; idx < 16384; idx += 256) sWo[idx] = g_WoT[idx];
    float bo[8];
    #pragma unroll
    for (int xi = 0; xi < 8; xi++) bo[xi] = b_out[xg * 8 + xi];

    float acc[4][8];
    #pragma unroll
    for (int a = 0; a < 4; a++)
        #pragma unroll
        for (int c = 0; c < 8; c++) acc[a][c] = 0.f;

    const float* src = g_hb + (size_t)(t + 1) * HB;
    for (int c = 0; c < 4; c++) {
        __syncthreads();
        for (int idx = tid; idx < 8192; idx += 256) sA[idx] = src[c * 8192 + idx];
        __syncthreads();
        #pragma unroll 4
        for (int hh = 0; hh < 64; hh++) {
            float4 a4 = *(const float4*)&sA[hh * BB + bgl * 4];
            const float* wr = &sWo[(c * 64 + hh) * XX + xg * 8];
            float4 w0 = *(const float4*)wr;
            float4 w1 = *(const float4*)(wr + 4);
            float av[4] = {a4.x, a4.y, a4.z, a4.w};
            float wv[8] = {w0.x, w0.y, w0.z, w0.w, w1.x, w1.y, w1.z, w1.w};
            #pragma unroll
            for (int bi = 0; bi < 4; bi++)
                #pragma unroll
                for (int xi = 0; xi < 8; xi++)
                    acc[bi][xi] += av[bi] * wv[xi];
        }
    }
    #pragma unroll
    for (int bi = 0; bi < 4; bi++) {
        int b = bgl * 4 + bi;
        float* dst = out + (size_t)b * TT * XX + (size_t)t * XX + xg * 8;
        #pragma unroll
        for (int xi = 0; xi < 8; xi++) dst[xi] = acc[bi][xi] + bo[xi];
    }
}

// ---------------- host launch ----------------
extern "C" void kernel_launch(void* const* d_in, const int* in_sizes, int n_in,
                              void* d_out, int out_size)
{
    const float* h_enc = (const float*)d_in[1];
    const float* W_ih  = (const float*)d_in[2];
    const float* W_hh  = (const float*)d_in[3];
    const float* b_ih  = (const float*)d_in[4];
    const float* b_hh  = (const float*)d_in[5];
    const float* W_out = (const float*)d_in[6];
    const float* b_out = (const float*)d_in[7];
    const int*   mask0 = (const int*)d_in[8];
    const int*   mask1 = (const int*)d_in[9];
    const int*   skipp = (n_in > 10) ? (const int*)d_in[10] : nullptr;

    cudaFuncSetAttribute(k_main, cudaFuncAttributeMaxDynamicSharedMemorySize, SMEM_MAIN);
    cudaFuncSetAttribute(k_out,  cudaFuncAttributeMaxDynamicSharedMemorySize, SMEM_OUT);

    k_wc<<<G3 + 64, 256>>>(W_ih, W_out);                               // launch 0
    k_init_tables<<<1, 256>>>(mask0, mask1, skipp, W_ih, b_ih, b_out); // launch 1
    k_init_state<<<128, 256>>>(h_enc, mask0);                          // launch 2
    k_main<<<128, NTH, SMEM_MAIN>>>(W_hh, b_ih, b_hh, h_enc);          // launch 3
    k_out<<<TT, 256, SMEM_OUT>>>((float*)d_out, b_out);                // launch 4
}

// round 6
// speedup vs baseline: 1.7150x; 1.7150x over previous
#include <cuda_runtime.h>
#include <math.h>

#define BB   128            // batch
#define TT   512            // time steps
#define HH   256            // hidden
#define XX   64             // feature / output
#define G3   768            // 3*H
#define HB   (HH * BB)      // 32768 floats per [h][b] map

// ---------------- device scratch (static: no runtime allocation) ----------------
__device__ float g_buf[(size_t)TT * HB];        // h_t history, [t][h][b]      (64 MB)
__device__ float g_hb [(size_t)(TT + 1) * HB];  // hb_{t-1} at slot t, slot0=0 (64 MB)
__device__ float g_hid[2 * HB];                 // double-buffered hidden_i [par][h][b]
__device__ float g_Wc [G3 * HH];                // W_ih @ W_out   [768][256]
__device__ float g_WoT[HH * XX];                // W_out transposed [h][x]
__device__ float g_bc [G3];                     // b_ih + W_ih @ b_out
__device__ float g_m0f[TT], g_m1f[TT];
__device__ int   g_gidx[TT], g_pidx[TT];        // -1 => zero placeholder
__device__ unsigned g_bcnt[8 * 32];             // per-group barrier counters (padded)
__device__ unsigned g_bgen[8 * 32];             // per-group generation (monotonic)

typedef unsigned long long ull;

// ---------------- packed f32x2 ops (Blackwell) ----------------
#define FMA2(d, a, b) asm("fma.rn.f32x2 %0, %1, %2, %3;" \
                          : "=l"(d) : "l"(a), "l"(b), "l"(d))
#define ADD2(d, a, b) asm("add.rn.f32x2 %0, %1, %2;" \
                          : "=l"(d) : "l"(a), "l"(b))
__device__ __forceinline__ float lo32(ull v) {
    return __uint_as_float((unsigned)(v & 0xffffffffull));
}
__device__ __forceinline__ float hi32(ull v) {
    return __uint_as_float((unsigned)(v >> 32));
}

// ---------------- acq/rel group barrier (no membar, no L1 flush) ----------------
__device__ __forceinline__ void group_barrier(unsigned* cnt, unsigned* gen, unsigned nctas)
{
    unsigned g;
    asm volatile("ld.relaxed.gpu.u32 %0, [%1];" : "=r"(g) : "l"(gen));
    unsigned old;
    asm volatile("atom.add.release.gpu.u32 %0, [%1], 1;" : "=r"(old) : "l"(cnt));
    if (old == nctas - 1u) {
        asm volatile("st.relaxed.gpu.u32 [%0], %1;" :: "l"(cnt), "r"(0u));
        asm volatile("st.release.gpu.u32 [%0], %1;" :: "l"(gen), "r"(g + 1u));
    } else {
        unsigned cur;
        do {
            asm volatile("ld.acquire.gpu.u32 %0, [%1];" : "=r"(cur) : "l"(gen));
        } while (cur == g);
    }
}

// ---------------- K_wc: Wc = W_ih @ W_out  + W_out transpose ----------------
__global__ void k_wc(const float* __restrict__ W_ih, const float* __restrict__ W_out)
{
    int j = blockIdx.x;
    int k = threadIdx.x;
    if (j < G3) {
        float acc = 0.f;
        #pragma unroll
        for (int x = 0; x < XX; x++)
            acc += W_ih[j * XX + x] * W_out[x * HH + k];
        g_Wc[j * HH + k] = acc;
    } else {
        int idx = (j - G3) * 256 + k;
        int h = idx >> 6, x = idx & 63;
        g_WoT[h * XX + x] = W_out[x * HH + h];
    }
}

// ---------------- K_tab: tables + composed bias ----------------
__global__ void k_init_tables(const int* __restrict__ mask0, const int* __restrict__ mask1,
                              const int* skipp,
                              const float* __restrict__ W_ih, const float* __restrict__ b_ih,
                              const float* __restrict__ b_out)
{
    int tid = threadIdx.x;
    int skip = skipp ? skipp[0] : 4;
    for (int i = tid; i < TT; i += 256) {
        g_m0f[i] = (float)mask0[i];
        g_m1f[i] = (float)mask1[i];
        int pg = (i < skip) ? 2 * i : i - skip;
        g_gidx[i] = (pg < skip) ? -1 : (pg - skip);
        int pp = (i < skip) ? 2 * i + 1 : i - skip;
        g_pidx[i] = (pp < skip) ? -1 : (pp - skip);
    }
    for (int j = tid; j < G3; j += 256) {
        float acc = b_ih[j];
        for (int x = 0; x < XX; x++) acc += W_ih[j * XX + x] * b_out[x];
        g_bc[j] = acc;
    }
}

// ---------------- K_state: init hidden_0 / hb_{-1} ----------------
__global__ void k_init_state(const float* __restrict__ h_enc, const int* __restrict__ mask0)
{
    int idx = blockIdx.x * 256 + threadIdx.x;   // 0..32767
    int h = idx >> 7, b = idx & 127;
    float m0 = (float)mask0[0];
    g_hid[h * BB + b] = m0 * h_enc[b * HH + h];
    g_hb[idx] = 0.f;
}

// ---------------- K_main: persistent recurrence, register-blocked 4b x 2h, k-split 8 ----
// thread: tid = hg*32 + kq*4 + bq   (hg 0..7 = warp, kq 0..7 = k slice, bq 0..3 = b quad)
// cells: h = h0 + hg*2 + {0,1},  b = b0 + bq*4 + {0..3},  k in [kq*32, kq*32+32)
// sW  [256k][128+swz]  : chunk for (k,hl) at k*128 + ((hl*8) ^ (((k>>5)&3)*8)), 6 used floats
// sAct[256k][40]       : 32 data floats at k*40 + ((k>>5)&1)*4,  (hid,hb) pairs per b
#define SW_F    (256 * 128)
#define SACT_F  (256 * 40)
#define SMEM_MAIN ((SW_F + SACT_F + 4 * TT) * 4)

__global__ void __launch_bounds__(256, 1)
k_main(const float* __restrict__ W_hh, const float* __restrict__ b_ih,
       const float* __restrict__ b_hh, const float* __restrict__ h_enc)
{
    extern __shared__ float sm[];
    float* sW   = sm;
    float* sAct = sW + SW_F;
    float* sM0  = sAct + SACT_F;
    float* sM1  = sM0 + TT;
    int*   sGI  = (int*)(sM1 + TT);
    int*   sPI  = sGI + TT;

    const int tid = threadIdx.x;
    const int bq  = tid & 3;
    const int kq  = (tid >> 2) & 7;
    const int hg  = tid >> 5;                   // warp id
    const int bg  = blockIdx.x >> 4;            // barrier group = batch group
    const int hgrp= blockIdx.x & 15;
    const int b0  = bg * 16;
    const int h0  = hgrp * 16;
    const int kb0 = kq & 1, kb1 = (kq >> 1) & 1, kb2 = kq >> 2;

    // owned cell for epilogue
    const int h_m   = h0 + hg * 2 + kb2;
    const int b_l   = bq * 4 + (kq & 3);
    const int b_m   = b0 + b_l;
    const int off   = h_m * BB + b_m;

    // ---- stage weight slice once ----
    for (int idx = tid; idx < 256 * 16; idx += 256) {
        int k = idx >> 4, hl = idx & 15;
        float* d = sW + (size_t)k * 128 + ((hl * 8) ^ (((k >> 5) & 3) * 8));
        #pragma unroll
        for (int g = 0; g < 3; g++) {
            int row = g * HH + h0 + hl;
            d[2 * g]     = W_hh[row * HH + k];
            d[2 * g + 1] = g_Wc[row * HH + k];
        }
    }
    for (int idx = tid; idx < TT; idx += 256) {
        sM0[idx] = g_m0f[idx]; sM1[idx] = g_m1f[idx];
        sGI[idx] = g_gidx[idx]; sPI[idx] = g_pidx[idx];
    }

    // per-owned-cell bias constants
    const float bhh_n = b_hh[2 * HH + h_m];
    const float cr0 = b_hh[h_m]      + b_ih[h_m];
    const float cz0 = b_hh[HH + h_m] + b_ih[HH + h_m];
    const float cn0 = b_ih[2 * HH + h_m];
    const float crN = b_hh[h_m]      + g_bc[h_m];
    const float czN = b_hh[HH + h_m] + g_bc[HH + h_m];
    const float cnN = g_bc[2 * HH + h_m];

    float h_prev = h_enc[b_m * HH + h_m];
    __syncthreads();

    unsigned* genp = &g_bgen[bg * 32];
    unsigned* cntp = &g_bcnt[bg * 32];

    const float* ap_base = sAct + (size_t)kq * 32 * 40 + (kq & 1) * 4 + bq * 8;
    const float* wp_base = sW + (size_t)kq * 32 * 128;
    const int c0 = (hg * 16) ^ ((kq & 3) * 8);
    const int c1 = c0 ^ 8;

    for (int i = 0; i < TT; i++) {
        // ---- tile load: conflict-free mapping (quarter covers k and k+32) ----
        const float* srcH = g_hid + (i & 1) * HB;
        const float* srcB = g_hb + (size_t)i * HB;
        #pragma unroll
        for (int r = 0; r < 4; r++) {
            int idx = r * 256 + tid;            // 1024 items
            int q  = idx & 3;
            int kp = (idx >> 2) & 1;
            int kl = (idx >> 3) & 31;
            int kh = idx >> 8;
            int k  = kh * 64 + kp * 32 + kl;
            float4 hv = __ldcg((const float4*)(srcH + k * BB + b0 + q * 4));
            float4 bv = __ldcg((const float4*)(srcB + k * BB + b0 + q * 4));
            float* d = sAct + (size_t)k * 40 + ((k >> 5) & 1) * 4 + q * 8;
            *(float4*)d       = make_float4(hv.x, bv.x, hv.y, bv.y);
            *(float4*)(d + 4) = make_float4(hv.z, bv.z, hv.w, bv.w);
        }
        __syncthreads();

        // ---- register-blocked fused dual GEMM over k slice ----
        ull acc[2][4][3];
        #pragma unroll
        for (int hh = 0; hh < 2; hh++)
            #pragma unroll
            for (int bb = 0; bb < 4; bb++)
                #pragma unroll
                for (int g = 0; g < 3; g++) acc[hh][bb][g] = 0ull;

        #pragma unroll 4
        for (int j = 0; j < 32; j++) {
            const float* a = ap_base + (size_t)j * 40;
            ulonglong2 aA = *(const ulonglong2*)a;
            ulonglong2 aB = *(const ulonglong2*)(a + 4);
            const float* wr = wp_base + (size_t)j * 128;
            ulonglong2 w0A = *(const ulonglong2*)(wr + c0);
            ull        w0n = *(const ull*)(wr + c0 + 4);
            ulonglong2 w1A = *(const ulonglong2*)(wr + c1);
            ull        w1n = *(const ull*)(wr + c1 + 4);
            ull av[4] = {aA.x, aA.y, aB.x, aB.y};
            #pragma unroll
            for (int bb = 0; bb < 4; bb++) {
                FMA2(acc[0][bb][0], av[bb], w0A.x);
                FMA2(acc[0][bb][1], av[bb], w0A.y);
                FMA2(acc[0][bb][2], av[bb], w0n);
                FMA2(acc[1][bb][0], av[bb], w1A.x);
                FMA2(acc[1][bb][1], av[bb], w1A.y);
                FMA2(acc[1][bb][2], av[bb], w1n);
            }
        }

        // ---- 3-level halving butterfly across k slices ----
        ull r1[2][2][3];
        #pragma unroll
        for (int hh = 0; hh < 2; hh++)
            #pragma unroll
            for (int bp = 0; bp < 2; bp++)
                #pragma unroll
                for (int g = 0; g < 3; g++) {
                    ull x = acc[hh][bp * 2][g], y = acc[hh][bp * 2 + 1][g];
                    ull give = kb0 ? x : y;
                    ull keep = kb0 ? y : x;
                    ull rec = __shfl_xor_sync(0xffffffffu, give, 4);
                    ADD2(r1[hh][bp][g], keep, rec);
                }
        ull r2[2][3];
        #pragma unroll
        for (int hh = 0; hh < 2; hh++)
            #pragma unroll
            for (int g = 0; g < 3; g++) {
                ull x = r1[hh][0][g], y = r1[hh][1][g];
                ull give = kb1 ? x : y;
                ull keep = kb1 ? y : x;
                ull rec = __shfl_xor_sync(0xffffffffu, give, 8);
                ADD2(r2[hh][g], keep, rec);
            }
        ull r3[3];
        #pragma unroll
        for (int g = 0; g < 3; g++) {
            ull x = r2[0][g], y = r2[1][g];
            ull give = kb2 ? x : y;
            ull keep = kb2 ? y : x;
            ull rec = __shfl_xor_sync(0xffffffffu, give, 16);
            ADD2(r3[g], keep, rec);
        }

        // ---- GRU epilogue: every thread owns exactly one cell ----
        {
            const float cbr = i ? crN : cr0;
            const float cbz = i ? czN : cz0;
            const float cbn = i ? cnN : cn0;
            float pre_r = lo32(r3[0]) + hi32(r3[0]) + cbr;
            float pre_z = lo32(r3[1]) + hi32(r3[1]) + cbz;
            float ghn   = lo32(r3[2]) + bhh_n;
            float rg = __fdividef(1.f, 1.f + __expf(-pre_r));
            float zg = __fdividef(1.f, 1.f + __expf(-pre_z));
            float pre_n = hi32(r3[2]) + cbn + rg * ghn;
            pre_n = fminf(fmaxf(pre_n, -15.f), 15.f);
            float e2 = __expf(2.f * pre_n);
            float ng = __fdividef(e2 - 1.f, e2 + 1.f);
            float hiddenv = sAct[(size_t)h_m * 40 + ((h_m >> 5) & 1) * 4 + b_l * 2];
            float h_new = (1.f - zg) * ng + zg * hiddenv;

            g_buf[(size_t)i * HB + off] = h_new;
            int pi_ = sPI[i];
            float sp = (pi_ < 0) ? 0.f : g_buf[(size_t)pi_ * HB + off];
            g_hb[(size_t)(i + 1) * HB + off] = h_prev + sp;
            int ip = i + 1;
            if (ip < TT) {
                int gi_ = sGI[ip];
                float sg = (gi_ < 0) ? 0.f : g_buf[(size_t)gi_ * HB + off];
                g_hid[(ip & 1) * HB + off] = sM0[ip] * h_new + sM1[ip] * sg;
            }
            h_prev = h_new;
        }

        // ---- group barrier (16 CTAs sharing this batch group) ----
        __syncthreads();
        if (tid == 0) group_barrier(cntp, genp, 16u);
        __syncthreads();
    }
}

// ---------------- K_out: out[b][t][x] = hb_t . W_out[x] + b_out ----------------
#define SMEM_OUT ((16384 + 8192) * 4)
__global__ void __launch_bounds__(256)
k_out(float* __restrict__ out, const float* __restrict__ b_out)
{
    extern __shared__ float s[];
    float* sWo = s;              // [256h][64x]
    float* sA  = s + 16384;      // [64h][128b]
    const int t = blockIdx.x;
    const int tid = threadIdx.x;
    const int bgl = tid & 31, xg = tid >> 5;

    for (int idx = tid; idx < 16384; idx += 256) sWo[idx] = g_WoT[idx];
    float bo[8];
    #pragma unroll
    for (int xi = 0; xi < 8; xi++) bo[xi] = b_out[xg * 8 + xi];

    float acc[4][8];
    #pragma unroll
    for (int a = 0; a < 4; a++)
        #pragma unroll
        for (int c = 0; c < 8; c++) acc[a][c] = 0.f;

    const float* src = g_hb + (size_t)(t + 1) * HB;
    for (int c = 0; c < 4; c++) {
        __syncthreads();
        for (int idx = tid; idx < 8192; idx += 256) sA[idx] = src[c * 8192 + idx];
        __syncthreads();
        #pragma unroll 4
        for (int hh = 0; hh < 64; hh++) {
            float4 a4 = *(const float4*)&sA[hh * BB + bgl * 4];
            const float* wr = &sWo[(c * 64 + hh) * XX + xg * 8];
            float4 w0 = *(const float4*)wr;
            float4 w1 = *(const float4*)(wr + 4);
            float av[4] = {a4.x, a4.y, a4.z, a4.w};
            float wv[8] = {w0.x, w0.y, w0.z, w0.w, w1.x, w1.y, w1.z, w1.w};
            #pragma unroll
            for (int bi = 0; bi < 4; bi++)
                #pragma unroll
                for (int xi = 0; xi < 8; xi++)
                    acc[bi][xi] += av[bi] * wv[xi];
        }
    }
    #pragma unroll
    for (int bi = 0; bi < 4; bi++) {
        int b = bgl * 4 + bi;
        float* dst = out + (size_t)b * TT * XX + (size_t)t * XX + xg * 8;
        #pragma unroll
        for (int xi = 0; xi < 8; xi++) dst[xi] = acc[bi][xi] + bo[xi];
    }
}

// ---------------- host launch ----------------
extern "C" void kernel_launch(void* const* d_in, const int* in_sizes, int n_in,
                              void* d_out, int out_size)
{
    const float* h_enc = (const float*)d_in[1];
    const float* W_ih  = (const float*)d_in[2];
    const float* W_hh  = (const float*)d_in[3];
    const float* b_ih  = (const float*)d_in[4];
    const float* b_hh  = (const float*)d_in[5];
    const float* W_out = (const float*)d_in[6];
    const float* b_out = (const float*)d_in[7];
    const int*   mask0 = (const int*)d_in[8];
    const int*   mask1 = (const int*)d_in[9];
    const int*   skipp = (n_in > 10) ? (const int*)d_in[10] : nullptr;

    cudaFuncSetAttribute(k_main, cudaFuncAttributeMaxDynamicSharedMemorySize, SMEM_MAIN);
    cudaFuncSetAttribute(k_out,  cudaFuncAttributeMaxDynamicSharedMemorySize, SMEM_OUT);

    k_wc<<<G3 + 64, 256>>>(W_ih, W_out);
    k_init_tables<<<1, 256>>>(mask0, mask1, skipp, W_ih, b_ih, b_out);
    k_init_state<<<128, 256>>>(h_enc, mask0);
    k_main<<<128, 256, SMEM_MAIN>>>(W_hh, b_ih, b_hh, h_enc);
    k_out<<<TT, 256, SMEM_OUT>>>((float*)d_out, b_out);
}

// round 7
// speedup vs baseline: 2.0110x; 1.1726x over previous
#include <cuda_runtime.h>
#include <math.h>

#define BB   128            // batch
#define TT   512            // time steps
#define HH   256            // hidden
#define XX   64             // feature / output
#define G3   768            // 3*H
#define HB   (HH * BB)      // 32768 floats per [h][b] map

// ---------------- device scratch (static: no runtime allocation) ----------------
__device__ float g_hb [(size_t)(TT + 1) * HB];  // hb_{t-1} at slot t, slot0=0 (64 MB)
__device__ float g_hid[2 * HB];                 // double-buffered hidden_i [par][h][b]
__device__ float g_Wc [G3 * HH];                // W_ih @ W_out   [768][256]
__device__ float g_WoT[HH * XX];                // W_out transposed [h][x]
__device__ float g_bc [G3];                     // b_ih + W_ih @ b_out
__device__ float g_m0f[TT], g_m1f[TT];
__device__ int   g_gidx[TT], g_pidx[TT];        // -1 => zero placeholder
__device__ unsigned g_ctr[8 * 32];              // per-group monotonic step counters

typedef unsigned long long ull;

// ---------------- packed f32x2 ops (Blackwell) ----------------
#define FMA2(d, a, b) asm("fma.rn.f32x2 %0, %1, %2, %3;" \
                          : "=l"(d) : "l"(a), "l"(b), "l"(d))
#define ADD2(d, a, b) asm("add.rn.f32x2 %0, %1, %2;" \
                          : "=l"(d) : "l"(a), "l"(b))
__device__ __forceinline__ float lo32(ull v) {
    return __uint_as_float((unsigned)(v & 0xffffffffull));
}
__device__ __forceinline__ float hi32(ull v) {
    return __uint_as_float((unsigned)(v >> 32));
}

// ---------------- K_wc: Wc = W_ih @ W_out  + W_out transpose ----------------
__global__ void k_wc(const float* __restrict__ W_ih, const float* __restrict__ W_out)
{
    int j = blockIdx.x;
    int k = threadIdx.x;
    if (j < G3) {
        float acc = 0.f;
        #pragma unroll
        for (int x = 0; x < XX; x++)
            acc += W_ih[j * XX + x] * W_out[x * HH + k];
        g_Wc[j * HH + k] = acc;
    } else {
        int idx = (j - G3) * 256 + k;
        int h = idx >> 6, x = idx & 63;
        g_WoT[h * XX + x] = W_out[x * HH + h];
    }
}

// ---------------- K_tab: tables + composed bias ----------------
__global__ void k_init_tables(const int* __restrict__ mask0, const int* __restrict__ mask1,
                              const int* skipp,
                              const float* __restrict__ W_ih, const float* __restrict__ b_ih,
                              const float* __restrict__ b_out)
{
    int tid = threadIdx.x;
    int skip = skipp ? skipp[0] : 4;
    for (int i = tid; i < TT; i += 256) {
        g_m0f[i] = (float)mask0[i];
        g_m1f[i] = (float)mask1[i];
        int pg = (i < skip) ? 2 * i : i - skip;
        g_gidx[i] = (pg < skip) ? -1 : (pg - skip);
        int pp = (i < skip) ? 2 * i + 1 : i - skip;
        g_pidx[i] = (pp < skip) ? -1 : (pp - skip);
    }
    for (int j = tid; j < G3; j += 256) {
        float acc = b_ih[j];
        for (int x = 0; x < XX; x++) acc += W_ih[j * XX + x] * b_out[x];
        g_bc[j] = acc;
    }
}

// ---------------- K_state: init hidden_0 / hb_{-1} / counters ----------------
__global__ void k_init_state(const float* __restrict__ h_enc, const int* __restrict__ mask0)
{
    int idx = blockIdx.x * 256 + threadIdx.x;   // 0..32767
    int h = idx >> 7, b = idx & 127;
    float m0 = (float)mask0[0];
    g_hid[h * BB + b] = m0 * h_enc[b * HH + h];
    g_hb[idx] = 0.f;
    if (idx < 8 * 32) g_ctr[idx] = 0u;
}

// ---------------- K_main: persistent recurrence, register-blocked 4b x 2h, k-split 8 ----
// thread: tid = hg*32 + kq*4 + bq   (hg 0..7 = warp, kq 0..7 = k slice, bq 0..3 = b quad)
// cells: h = h0 + hg*2 + {0,1},  b = b0 + bq*4 + {0..3},  k in [kq*32, kq*32+32)
// sW  [256k][128+swz]  : chunk for (k,hl) at k*128 + ((hl*8) ^ (((k>>5)&3)*8)), 6 used floats
// sAct[256k][40]       : 32 data floats at k*40 + ((k>>5)&1)*4,  (hid,hb) pairs per b
// sHist[16][256]       : per-thread ring of last h values (same-cell skip reads)
#define SW_F    (256 * 128)
#define SACT_F  (256 * 40)
#define SHIST_F (16 * 256)
#define SMEM_MAIN ((SW_F + SACT_F + SHIST_F + 4 * TT) * 4)

__global__ void __launch_bounds__(256, 1)
k_main(const float* __restrict__ W_hh, const float* __restrict__ b_ih,
       const float* __restrict__ b_hh, const float* __restrict__ h_enc)
{
    extern __shared__ float sm[];
    float* sW    = sm;
    float* sAct  = sW + SW_F;
    float* sHist = sAct + SACT_F;
    float* sM0   = sHist + SHIST_F;
    float* sM1   = sM0 + TT;
    int*   sGI   = (int*)(sM1 + TT);
    int*   sPI   = sGI + TT;

    const int tid = threadIdx.x;
    const int bq  = tid & 3;
    const int kq  = (tid >> 2) & 7;
    const int hg  = tid >> 5;                   // warp id
    const int bg  = blockIdx.x >> 4;            // barrier group = batch group
    const int hgrp= blockIdx.x & 15;
    const int b0  = bg * 16;
    const int h0  = hgrp * 16;
    const int kb0 = kq & 1, kb1 = (kq >> 1) & 1, kb2 = kq >> 2;

    // owned cell for epilogue
    const int h_m   = h0 + hg * 2 + kb2;
    const int b_l   = bq * 4 + (kq & 3);
    const int b_m   = b0 + b_l;
    const int off   = h_m * BB + b_m;

    // ---- stage weight slice once ----
    for (int idx = tid; idx < 256 * 16; idx += 256) {
        int k = idx >> 4, hl = idx & 15;
        float* d = sW + (size_t)k * 128 + ((hl * 8) ^ (((k >> 5) & 3) * 8));
        #pragma unroll
        for (int g = 0; g < 3; g++) {
            int row = g * HH + h0 + hl;
            d[2 * g]     = W_hh[row * HH + k];
            d[2 * g + 1] = g_Wc[row * HH + k];
        }
    }
    for (int idx = tid; idx < TT; idx += 256) {
        sM0[idx] = g_m0f[idx]; sM1[idx] = g_m1f[idx];
        sGI[idx] = g_gidx[idx]; sPI[idx] = g_pidx[idx];
    }

    // per-owned-cell bias constants
    const float bhh_n = b_hh[2 * HH + h_m];
    const float cr0 = b_hh[h_m]      + b_ih[h_m];
    const float cz0 = b_hh[HH + h_m] + b_ih[HH + h_m];
    const float cn0 = b_ih[2 * HH + h_m];
    const float crN = b_hh[h_m]      + g_bc[h_m];
    const float czN = b_hh[HH + h_m] + g_bc[HH + h_m];
    const float cnN = g_bc[2 * HH + h_m];

    float h_prev  = h_enc[b_m * HH + h_m];
    float m00;
    {   // hidden_0 own-cell value (skip term is zero at step 0)
        m00 = g_m0f[0];
    }
    float hid_own = m00 * h_prev;
    __syncthreads();

    unsigned* ctrp = &g_ctr[bg * 32];

    const float* ap_base = sAct + (size_t)kq * 32 * 40 + (kq & 1) * 4 + bq * 8;
    const float* wp_base = sW + (size_t)kq * 32 * 128;
    const int c0 = (hg * 16) ^ ((kq & 3) * 8);
    const int c1 = c0 ^ 8;

    for (int i = 0; i < TT; i++) {
        // ---- tile load: conflict-free mapping (quarter covers k and k+32) ----
        const float* srcH = g_hid + (i & 1) * HB;
        const float* srcB = g_hb + (size_t)i * HB;
        #pragma unroll
        for (int r = 0; r < 4; r++) {
            int idx = r * 256 + tid;            // 1024 items
            int q  = idx & 3;
            int kp = (idx >> 2) & 1;
            int kl = (idx >> 3) & 31;
            int kh = idx >> 8;
            int k  = kh * 64 + kp * 32 + kl;
            float4 hv = __ldcg((const float4*)(srcH + k * BB + b0 + q * 4));
            float4 bv = __ldcg((const float4*)(srcB + k * BB + b0 + q * 4));
            float* d = sAct + (size_t)k * 40 + ((k >> 5) & 1) * 4 + q * 8;
            *(float4*)d       = make_float4(hv.x, bv.x, hv.y, bv.y);
            *(float4*)(d + 4) = make_float4(hv.z, bv.z, hv.w, bv.w);
        }
        __syncthreads();

        // ---- register-blocked fused dual GEMM over k slice ----
        ull acc[2][4][3];
        #pragma unroll
        for (int hh = 0; hh < 2; hh++)
            #pragma unroll
            for (int bb = 0; bb < 4; bb++)
                #pragma unroll
                for (int g = 0; g < 3; g++) acc[hh][bb][g] = 0ull;

        #pragma unroll 4
        for (int j = 0; j < 32; j++) {
            const float* a = ap_base + (size_t)j * 40;
            ulonglong2 aA = *(const ulonglong2*)a;
            ulonglong2 aB = *(const ulonglong2*)(a + 4);
            const float* wr = wp_base + (size_t)j * 128;
            ulonglong2 w0A = *(const ulonglong2*)(wr + c0);
            ull        w0n = *(const ull*)(wr + c0 + 4);
            ulonglong2 w1A = *(const ulonglong2*)(wr + c1);
            ull        w1n = *(const ull*)(wr + c1 + 4);
            ull av[4] = {aA.x, aA.y, aB.x, aB.y};
            #pragma unroll
            for (int bb = 0; bb < 4; bb++) {
                FMA2(acc[0][bb][0], av[bb], w0A.x);
                FMA2(acc[0][bb][1], av[bb], w0A.y);
                FMA2(acc[0][bb][2], av[bb], w0n);
                FMA2(acc[1][bb][0], av[bb], w1A.x);
                FMA2(acc[1][bb][1], av[bb], w1A.y);
                FMA2(acc[1][bb][2], av[bb], w1n);
            }
        }

        // ---- 3-level halving butterfly across k slices ----
        ull r1[2][2][3];
        #pragma unroll
        for (int hh = 0; hh < 2; hh++)
            #pragma unroll
            for (int bp = 0; bp < 2; bp++)
                #pragma unroll
                for (int g = 0; g < 3; g++) {
                    ull x = acc[hh][bp * 2][g], y = acc[hh][bp * 2 + 1][g];
                    ull give = kb0 ? x : y;
                    ull keep = kb0 ? y : x;
                    ull rec = __shfl_xor_sync(0xffffffffu, give, 4);
                    ADD2(r1[hh][bp][g], keep, rec);
                }
        ull r2[2][3];
        #pragma unroll
        for (int hh = 0; hh < 2; hh++)
            #pragma unroll
            for (int g = 0; g < 3; g++) {
                ull x = r1[hh][0][g], y = r1[hh][1][g];
                ull give = kb1 ? x : y;
                ull keep = kb1 ? y : x;
                ull rec = __shfl_xor_sync(0xffffffffu, give, 8);
                ADD2(r2[hh][g], keep, rec);
            }
        ull r3[3];
        #pragma unroll
        for (int g = 0; g < 3; g++) {
            ull x = r2[0][g], y = r2[1][g];
            ull give = kb2 ? x : y;
            ull keep = kb2 ? y : x;
            ull rec = __shfl_xor_sync(0xffffffffu, give, 16);
            ADD2(r3[g], keep, rec);
        }

        // ---- GRU epilogue: every thread owns exactly one cell ----
        {
            const float cbr = i ? crN : cr0;
            const float cbz = i ? czN : cz0;
            const float cbn = i ? cnN : cn0;
            float pre_r = lo32(r3[0]) + hi32(r3[0]) + cbr;
            float pre_z = lo32(r3[1]) + hi32(r3[1]) + cbz;
            float ghn   = lo32(r3[2]) + bhh_n;
            float rg = __fdividef(1.f, 1.f + __expf(-pre_r));
            float zg = __fdividef(1.f, 1.f + __expf(-pre_z));
            float pre_n = hi32(r3[2]) + cbn + rg * ghn;
            pre_n = fminf(fmaxf(pre_n, -15.f), 15.f);
            float e2 = __expf(2.f * pre_n);
            float ng = __fdividef(e2 - 1.f, e2 + 1.f);
            float h_new = (1.f - zg) * ng + zg * hid_own;

            // same-thread skip history ring (16 slots; all delays <= 8)
            sHist[(i & 15) * 256 + tid] = h_new;
            int pi_ = sPI[i];
            float sp = (pi_ < 0) ? 0.f : sHist[(pi_ & 15) * 256 + tid];
            g_hb[(size_t)(i + 1) * HB + off] = h_prev + sp;
            int ip = i + 1;
            if (ip < TT) {
                int gi_ = sGI[ip];
                float sg = (gi_ < 0) ? 0.f : sHist[(gi_ & 15) * 256 + tid];
                float hidn = sM0[ip] * h_new + sM1[ip] * sg;
                g_hid[(ip & 1) * HB + off] = hidn;
                hid_own = hidn;
            }
            h_prev = h_new;
        }

        // ---- group sync: release-arrive once per CTA, all threads acquire-poll ----
        __syncthreads();                        // all stores above issued
        if (tid == 0)
            asm volatile("red.release.gpu.global.add.u32 [%0], %1;"
                         :: "l"(ctrp), "r"(1u) : "memory");
        unsigned tgt = 16u * (unsigned)(i + 1);
        unsigned v;
        do {
            asm volatile("ld.acquire.gpu.u32 %0, [%1];" : "=r"(v) : "l"(ctrp));
        } while ((int)(v - tgt) < 0);
    }
}

// ---------------- K_out: out[b][t][x] = hb_t . W_out[x] + b_out ----------------
#define SMEM_OUT ((16384 + 8192) * 4)
__global__ void __launch_bounds__(256)
k_out(float* __restrict__ out, const float* __restrict__ b_out)
{
    extern __shared__ float s[];
    float* sWo = s;              // [256h][64x]
    float* sA  = s + 16384;      // [64h][128b]
    const int t = blockIdx.x;
    const int tid = threadIdx.x;
    const int bgl = tid & 31, xg = tid >> 5;

    for (int idx = tid; idx < 16384; idx += 256) sWo[idx] = g_WoT[idx];
    float bo[8];
    #pragma unroll
    for (int xi = 0; xi < 8; xi++) bo[xi] = b_out[xg * 8 + xi];

    float acc[4][8];
    #pragma unroll
    for (int a = 0; a < 4; a++)
        #pragma unroll
        for (int c = 0; c < 8; c++) acc[a][c] = 0.f;

    const float* src = g_hb + (size_t)(t + 1) * HB;
    for (int c = 0; c < 4; c++) {
        __syncthreads();
        for (int idx = tid; idx < 8192; idx += 256) sA[idx] = src[c * 8192 + idx];
        __syncthreads();
        #pragma unroll 4
        for (int hh = 0; hh < 64; hh++) {
            float4 a4 = *(const float4*)&sA[hh * BB + bgl * 4];
            const float* wr = &sWo[(c * 64 + hh) * XX + xg * 8];
            float4 w0 = *(const float4*)wr;
            float4 w1 = *(const float4*)(wr + 4);
            float av[4] = {a4.x, a4.y, a4.z, a4.w};
            float wv[8] = {w0.x, w0.y, w0.z, w0.w, w1.x, w1.y, w1.z, w1.w};
            #pragma unroll
            for (int bi = 0; bi < 4; bi++)
                #pragma unroll
                for (int xi = 0; xi < 8; xi++)
                    acc[bi][xi] += av[bi] * wv[xi];
        }
    }
    #pragma unroll
    for (int bi = 0; bi < 4; bi++) {
        int b = bgl * 4 + bi;
        float* dst = out + (size_t)b * TT * XX + (size_t)t * XX + xg * 8;
        #pragma unroll
        for (int xi = 0; xi < 8; xi++) dst[xi] = acc[bi][xi] + bo[xi];
    }
}

// ---------------- host launch ----------------
extern "C" void kernel_launch(void* const* d_in, const int* in_sizes, int n_in,
                              void* d_out, int out_size)
{
    const float* h_enc = (const float*)d_in[1];
    const float* W_ih  = (const float*)d_in[2];
    const float* W_hh  = (const float*)d_in[3];
    const float* b_ih  = (const float*)d_in[4];
    const float* b_hh  = (const float*)d_in[5];
    const float* W_out = (const float*)d_in[6];
    const float* b_out = (const float*)d_in[7];
    const int*   mask0 = (const int*)d_in[8];
    const int*   mask1 = (const int*)d_in[9];
    const int*   skipp = (n_in > 10) ? (const int*)d_in[10] : nullptr;

    cudaFuncSetAttribute(k_main, cudaFuncAttributeMaxDynamicSharedMemorySize, SMEM_MAIN);
    cudaFuncSetAttribute(k_out,  cudaFuncAttributeMaxDynamicSharedMemorySize, SMEM_OUT);

    k_wc<<<G3 + 64, 256>>>(W_ih, W_out);
    k_init_tables<<<1, 256>>>(mask0, mask1, skipp, W_ih, b_ih, b_out);
    k_init_state<<<128, 256>>>(h_enc, mask0);
    k_main<<<128, 256, SMEM_MAIN>>>(W_hh, b_ih, b_hh, h_enc);
    k_out<<<TT, 256, SMEM_OUT>>>((float*)d_out, b_out);
}